// round 17
// baseline (speedup 1.0000x reference)
#include <cuda_runtime.h>
#include <cuda_fp16.h>

#define HH 2048
#define WW 2048
#define OUTCOLS 30                  // output columns per warp (lanes 1..30)
#define NSTRIPS 69                  // ceil(2048 / 30)
#define SEGROWS 16                  // output rows per warp segment
#define NSEGY (HH / SEGROWS)        // 128
#define NWARPS (NSTRIPS * NSEGY)    // 8832
#define TPB 256
#define WPB (TPB / 32)
#define NBLOCKS (NWARPS / WPB)      // 1104
#define WW4 (WW * 4)                // float4 elements per image row

struct HV { uint4 a, b; };          // one pixel: 16 ch normalized fp16 (8 half2)

__device__ __forceinline__ float dot4(float4 a, float4 b) {
    return a.x * b.x + a.y * b.y + a.z * b.z + a.w * b.w;
}

__device__ __forceinline__ unsigned h2u(half2 h) {
    return *(const unsigned*)&h;
}

// Two 4-deep fp16 chains + f32 combine (same numerics as prior rounds).
__device__ __forceinline__ float hdot(const HV& x, const HV& y) {
    const half2* hx = (const half2*)&x;
    const half2* hy = (const half2*)&y;
    half2 c0 = __hmul2(hx[0], hy[0]);
    c0 = __hfma2(hx[1], hy[1], c0);
    c0 = __hfma2(hx[2], hy[2], c0);
    c0 = __hfma2(hx[3], hy[3], c0);
    half2 c1 = __hmul2(hx[4], hy[4]);
    c1 = __hfma2(hx[5], hy[5], c1);
    c1 = __hfma2(hx[6], hy[6], c1);
    c1 = __hfma2(hx[7], hy[7], c1);
    float2 f0 = __half22float2(c0);
    float2 f1 = __half22float2(c1);
    return (f0.x + f0.y) + (f1.x + f1.y);
}

__device__ __forceinline__ HV shfl_down_hv(const HV& v) {
    HV r;
    const unsigned* s = (const unsigned*)&v;
    unsigned* d = (unsigned*)&r;
    #pragma unroll
    for (int j = 0; j < 8; j++)
        d[j] = __shfl_down_sync(0xffffffffu, s[j], 1);
    return r;
}

// Coalesced row (lane holds chunk lane&3 of pixel 8j+(lane>>2) in rw[j])
// -> 4-lane partial-norm reduce -> fp16 pack -> smem transpose -> lane owns
// its whole pixel (pixel index == lane).
__device__ __forceinline__ HV xpose_norm(const float4 rw[4],
                                         unsigned char* sb, int lane) {
    #pragma unroll
    for (int j = 0; j < 4; j++) {
        float s = dot4(rw[j], rw[j]);
        s += __shfl_xor_sync(0xffffffffu, s, 1);
        s += __shfl_xor_sync(0xffffffffu, s, 2);
        float inv = rsqrtf(fmaxf(s, 1e-24f));   // all-zero pixel stays zero
        half2 h0 = __floats2half2_rn(rw[j].x * inv, rw[j].y * inv);
        half2 h1 = __floats2half2_rn(rw[j].z * inv, rw[j].w * inv);
        *(uint2*)(sb + (unsigned)lane * 8u + 256u * j) =
            make_uint2(h2u(h0), h2u(h1));
    }
    __syncwarp();
    HV o;
    o.a = *(const uint4*)(sb + (unsigned)lane * 32u);
    o.b = *(const uint4*)(sb + (unsigned)lane * 32u + 16u);
    return o;
}

__global__ __launch_bounds__(TPB, 5)
void cos_sim_kernel(const float* __restrict__ img, float* __restrict__ out) {
    __shared__ __align__(16) unsigned char sbuf[WPB][2][1024];

    const int lane = threadIdx.x & 31;
    const int wib  = threadIdx.x >> 5;
    const int gw   = blockIdx.x * WPB + wib;
    const int strip = gw >> 7;               // / NSEGY (128)
    const int segy  = gw & (NSEGY - 1);
    const int pix0  = strip * OUTCOLS - 1;   // pixel column of lane 0
    const int col   = pix0 + lane;
    const bool writer = (lane >= 1) && (lane <= OUTCOLS) && (col < WW);
    const int rtop  = segy * SEGROWS;

    // Per-lane load geometry: single base offset + 32j immediates.
    // Predicated-off lanes never access memory, so no clamping needed.
    const int off0 = (pix0 + (lane >> 2)) * 4 + (lane & 3);
    bool val[4];
    #pragma unroll
    for (int j = 0; j < 4; j++)
        val[j] = (unsigned)(pix0 + 8 * j + (lane >> 2)) < WW;

    const float4* __restrict__ img4 = (const float4*)img;
    unsigned char* b0 = sbuf[wib][0];
    unsigned char* b1 = sbuf[wib][1];

    float4 rw[4];
    auto loadrow = [&](const float4* rp, bool rok) {
        #pragma unroll
        for (int j = 0; j < 4; j++) {
            float4 v = make_float4(0.f, 0.f, 0.f, 0.f);
            if (rok && val[j]) v = rp[off0 + 32 * j];
            rw[j] = v;
        }
    };

    // Prime: prev = row rtop-1, cur = row rtop.
    loadrow(img4 + (long long)(rtop - 1) * WW4, rtop > 0);
    HV prev = xpose_norm(rw, b0, lane);
    loadrow(img4 + (long long)rtop * WW4, true);
    HV cur = xpose_norm(rw, b1, lane);

    const float4* rp = img4 + (long long)(rtop + 1) * WW4;
    float* op = out + (size_t)rtop * WW + col;
    float up_acc = 0.0f;

    // Pair k handles rows (rtop+k-1, rtop+k); 17 pairs finalize 16 outputs.
    #pragma unroll 1
    for (int k = 0; k <= SEGROWS; k++) {
        loadrow(rp, (k < SEGROWS) & (rtop + k + 1 < HH));  // prefetch next row
        rp += WW4;

        HV curp = shfl_down_hv(cur);                 // cur[c+1]
        float A = hdot(prev, curp);                  // dot(prev[c],   cur[c+1])
        HV prevp = shfl_down_hv(prev);               // prev[c+1] (recomputed)
        float Z = hdot(prevp, cur);                  // dot(prev[c+1], cur[c])
        float B  = __shfl_up_sync(0xffffffffu, Z, 1);  // Z[c-1] = dot(prev[c], cur[c-1])
        float Au = __shfl_up_sync(0xffffffffu, A, 1);  // A[c-1]

        if (k > 0) {                                 // finalize out(rtop+k-1, col)
            if (writer) *op = up_acc + A + B;
            op += WW;
        }
        up_acc = Au + Z;                             // up-pair sum for next row
        prev = cur;
        if (k < SEGROWS)
            cur = xpose_norm(rw, (k & 1) ? b1 : b0, lane);
    }
}

extern "C" void kernel_launch(void* const* d_in, const int* in_sizes, int n_in,
                              void* d_out, int out_size) {
    const float* img = (const float*)d_in[0];
    float* out = (float*)d_out;
    cos_sim_kernel<<<NBLOCKS, TPB>>>(img, out);
}